// round 16
// baseline (speedup 1.0000x reference)
#include <cuda_runtime.h>
#include <cuda_fp16.h>
#include <cstdint>

#define BB 8
#define LQ 2048
#define LM 2048
#define DD 1024
#define NEGV (-1000000.0f)

// fixed-point scales (16-bit, 2x s8 limbs)
#define SQF  10240.0f
#define SMF  5632.0f
#define INVS (1.0f / (SQF * SMF))
#define QCLAMP 32639   // 127*256+127

// ------------------------- scratch (device globals) -------------------------
__device__ __half  g_qryh[(size_t)BB*LQ*DD], g_qryl[(size_t)BB*LQ*DD];
__device__ __half  g_Wh[(size_t)DD*DD],      g_Wl[(size_t)DD*DD];
__device__ int8_t  g_qh8[(size_t)BB*LQ*DD],  g_ql8[(size_t)BB*LQ*DD];   // q limbs, K-major
__device__ int8_t  g_mh8[(size_t)BB*LM*DD],  g_ml8[(size_t)BB*LM*DD];   // m limbs, K-major
__device__ __half  g_mTh[(size_t)BB*DD*LM];                              // m transposed fp16
__device__ float   g_logits[(size_t)BB*LQ*LM];
__device__ __half  g_w[(size_t)BB*LQ*LM];                                // softmax weights fp16

// ------------------------- helpers -------------------------
__device__ __forceinline__ uint32_t smem_u32(const void* p) {
    uint32_t a;
    asm("{ .reg .u64 t; cvta.to.shared.u64 t, %1; cvt.u32.u64 %0, t; }" : "=r"(a) : "l"(p));
    return a;
}
__device__ __forceinline__ void cp16(uint32_t s, const void* g) {
    asm volatile("cp.async.cg.shared.global [%0], [%1], 16;" :: "r"(s), "l"(g));
}
__device__ __forceinline__ void ldmx4(uint32_t* r, uint32_t a) {
    asm volatile("ldmatrix.sync.aligned.m8n8.x4.shared.b16 {%0,%1,%2,%3}, [%4];"
                 : "=r"(r[0]), "=r"(r[1]), "=r"(r[2]), "=r"(r[3]) : "r"(a));
}
__device__ __forceinline__ void mma16816(float* c, const uint32_t* a, uint32_t b0, uint32_t b1) {
    asm volatile(
        "mma.sync.aligned.m16n8k16.row.col.f32.f16.f16.f32 "
        "{%0,%1,%2,%3}, {%4,%5,%6,%7}, {%8,%9}, {%0,%1,%2,%3};"
        : "+f"(c[0]), "+f"(c[1]), "+f"(c[2]), "+f"(c[3])
        : "r"(a[0]), "r"(a[1]), "r"(a[2]), "r"(a[3]), "r"(b0), "r"(b1));
}
__device__ __forceinline__ void mma16816h(uint32_t* c, const uint32_t* a, uint32_t b0, uint32_t b1) {
    asm volatile(
        "mma.sync.aligned.m16n8k16.row.col.f16.f16.f16.f16 "
        "{%0,%1}, {%2,%3,%4,%5}, {%6,%7}, {%0,%1};"
        : "+r"(c[0]), "+r"(c[1])
        : "r"(a[0]), "r"(a[1]), "r"(a[2]), "r"(a[3]), "r"(b0), "r"(b1));
}
// int8 k32 MMA, s32 accumulate
__device__ __forceinline__ void mma_s8(int* c, const uint32_t* a, uint32_t b0, uint32_t b1) {
    asm volatile(
        "mma.sync.aligned.m16n8k32.row.col.s32.s8.s8.s32 "
        "{%0,%1,%2,%3}, {%4,%5,%6,%7}, {%8,%9}, {%0,%1,%2,%3};"
        : "+r"(c[0]), "+r"(c[1]), "+r"(c[2]), "+r"(c[3])
        : "r"(a[0]), "r"(a[1]), "r"(a[2]), "r"(a[3]), "r"(b0), "r"(b1));
}
__device__ __forceinline__ void split2h(float v, __half& h, __half& l) {
    h = __float2half_rn(v);
    l = __float2half_rn(v - __half2float(h));
}
// fixed-point split: v*scale -> (hi,lo) s8 limbs
__device__ __forceinline__ void split2q(float v, float scale, int& h, int& l) {
    int qi = __float2int_rn(v * scale);
    qi = max(-QCLAMP, min(QCLAMP, qi));
    l = ((qi + 128) & 255) - 128;
    h = (qi - l) >> 8;
}

// ======================= fp16 split GEMM (GEMM1 / GEMM3) =======================
// CTA 128(M) x 256(N), 256 thr = 8 warps (2x4), warp tile 64x64, K-chunk 64, 2 stages.
// MODE 1: main f32-acc + f16-acc corrections; +bias; quantize -> s8 limb planes
// MODE 3: C = A1·B1^T, 1-term f32-acc, plain, out fp32

#define ROWB 128
#define ATILEB (128 * ROWB)
#define BTILEB (256 * ROWB)
#define STAGEB (2*ATILEB + 2*BTILEB)   // 98304
#define NSTAGE 2

__device__ __forceinline__ void load_tileA(uint32_t st, const __half* g, int K, int k0, int tid) {
    #pragma unroll
    for (int p = 0; p < 4; p++) {
        int idx = p * 256 + tid;
        int row = idx >> 3, c = idx & 7;
        cp16(st + (uint32_t)row * ROWB + (uint32_t)((c ^ (row & 7)) << 4),
             g + (size_t)row * K + k0 + c * 8);
    }
}
__device__ __forceinline__ void load_tileB(uint32_t st, const __half* g, int K, int k0, int tid) {
    #pragma unroll
    for (int p = 0; p < 8; p++) {
        int idx = p * 256 + tid;
        int row = idx >> 3, c = idx & 7;
        cp16(st + (uint32_t)row * ROWB + (uint32_t)((c ^ (row & 7)) << 4),
             g + (size_t)row * K + k0 + c * 8);
    }
}

template<int MODE>
__global__ __launch_bounds__(256)
void gemm_f16(const __half* __restrict__ A1, const __half* __restrict__ A2,
              const __half* __restrict__ B1, const __half* __restrict__ B2,
              const float* __restrict__ bias,
              float* __restrict__ Cf, int8_t* __restrict__ Q8h, int8_t* __restrict__ Q8l,
              int N, int K, size_t sA, size_t sB, size_t sC)
{
    extern __shared__ __align__(128) char dynsmem[];
    const int tid  = threadIdx.x;
    const int bz   = blockIdx.z;
    const int bm   = blockIdx.y * 128;
    const int bn   = blockIdx.x * 256;
    const int wid  = tid >> 5;
    const int lane = tid & 31;
    const int wm   = (wid >> 2) * 64;
    const int wn   = (wid & 3) * 64;

    const uint32_t sb = smem_u32(dynsmem);

    const __half* pA1 = A1 + (size_t)bz * sA + (size_t)bm * K;
    const __half* pA2 = (MODE == 1) ? A2 + (size_t)bz * sA + (size_t)bm * K : nullptr;
    const __half* pB1 = B1 + (size_t)bz * sB + (size_t)bn * K;
    const __half* pB2 = (MODE == 1) ? B2 + (size_t)bz * sB + (size_t)bn * K : nullptr;

    float acc[4][8][4];
    #pragma unroll
    for (int i = 0; i < 4; i++)
        #pragma unroll
        for (int j = 0; j < 8; j++)
            #pragma unroll
            for (int r = 0; r < 4; r++) acc[i][j][r] = 0.0f;

    uint32_t facc[4][8][2];
    if (MODE == 1) {
        #pragma unroll
        for (int i = 0; i < 4; i++)
            #pragma unroll
            for (int j = 0; j < 8; j++) { facc[i][j][0] = 0u; facc[i][j][1] = 0u; }
    }

    const int nk = K >> 6;

    {
        load_tileA(sb, pA1, K, 0, tid);
        if (MODE == 1) load_tileA(sb + ATILEB, pA2, K, 0, tid);
        load_tileB(sb + 2*ATILEB, pB1, K, 0, tid);
        if (MODE == 1) load_tileB(sb + 2*ATILEB + BTILEB, pB2, K, 0, tid);
        asm volatile("cp.async.commit_group;" ::: "memory");
    }

    const uint32_t rowoff = (uint32_t)(lane & 15) * ROWB;
    const int      key    = lane & 7;
    const int      cbase  = lane >> 4;

    for (int c = 0; c < nk; ++c) {
        asm volatile("cp.async.wait_group 0;" ::: "memory");
        __syncthreads();

        if (c + 1 < nk) {
            uint32_t st = sb + (uint32_t)((c + 1) & 1) * STAGEB;
            int k0 = (c + 1) << 6;
            load_tileA(st, pA1, K, k0, tid);
            if (MODE == 1) load_tileA(st + ATILEB, pA2, K, k0, tid);
            load_tileB(st + 2*ATILEB, pB1, K, k0, tid);
            if (MODE == 1) load_tileB(st + 2*ATILEB + BTILEB, pB2, K, k0, tid);
            asm volatile("cp.async.commit_group;" ::: "memory");
        }

        const uint32_t st = sb + (uint32_t)(c & 1) * STAGEB;
        const uint32_t aH = st + (uint32_t)wm * ROWB + rowoff;
        const uint32_t aL = aH + ATILEB;
        const uint32_t bH = st + 2*ATILEB + (uint32_t)wn * ROWB + rowoff;
        const uint32_t bL = bH + BTILEB;

        #pragma unroll
        for (int kk = 0; kk < 4; kk++) {
            const uint32_t sw = (uint32_t)(((kk*2 + cbase) ^ key) << 4);
            uint32_t a1[4][4], b1[4][4];
            #pragma unroll
            for (int h = 0; h < 4; h++) ldmx4(b1[h], bH + (uint32_t)h * (16 * ROWB) + sw);
            #pragma unroll
            for (int mt = 0; mt < 4; mt++) ldmx4(a1[mt], aH + (uint32_t)mt * (16 * ROWB) + sw);

            #pragma unroll
            for (int mt = 0; mt < 4; mt++)
                #pragma unroll
                for (int nt = 0; nt < 8; nt++) {
                    const int g = nt >> 1, s = nt & 1;
                    mma16816(acc[mt][nt], a1[mt], b1[g][s], b1[g][s + 2]);
                }

            if (MODE == 1) {
                {
                    uint32_t a2[4][4];
                    #pragma unroll
                    for (int mt = 0; mt < 4; mt++) ldmx4(a2[mt], aL + (uint32_t)mt * (16 * ROWB) + sw);
                    #pragma unroll
                    for (int mt = 0; mt < 4; mt++)
                        #pragma unroll
                        for (int nt = 0; nt < 8; nt++) {
                            const int g = nt >> 1, s = nt & 1;
                            mma16816h(facc[mt][nt], a2[mt], b1[g][s], b1[g][s + 2]);
                        }
                }
                {
                    uint32_t b2[4][4];
                    #pragma unroll
                    for (int h = 0; h < 4; h++) ldmx4(b2[h], bL + (uint32_t)h * (16 * ROWB) + sw);
                    #pragma unroll
                    for (int mt = 0; mt < 4; mt++)
                        #pragma unroll
                        for (int nt = 0; nt < 8; nt++) {
                            const int g = nt >> 1, s = nt & 1;
                            mma16816h(facc[mt][nt], a1[mt], b2[g][s], b2[g][s + 2]);
                        }
                }
            }
        }
    }

    const int r0 = lane >> 2;
    const int c0 = (lane & 3) * 2;

    #pragma unroll
    for (int mt = 0; mt < 4; mt++) {
        #pragma unroll
        for (int half_ = 0; half_ < 2; half_++) {
            const size_t grow = (size_t)(bm + wm + mt * 16 + r0 + half_ * 8);
            #pragma unroll
            for (int nt = 0; nt < 8; nt++) {
                const int gcol = bn + wn + nt * 8 + c0;
                float v0 = acc[mt][nt][half_ * 2 + 0];
                float v1 = acc[mt][nt][half_ * 2 + 1];

                if (MODE == 1) {
                    __half2 h2 = *reinterpret_cast<__half2*>(&facc[mt][nt][half_]);
                    v0 += __half2float(__low2half(h2))  + bias[gcol];
                    v1 += __half2float(__high2half(h2)) + bias[gcol + 1];
                    int h0, l0, h1, l1;
                    split2q(v0, SQF, h0, l0);
                    split2q(v1, SQF, h1, l1);
                    uint16_t ph = (uint16_t)((h0 & 255) | ((h1 & 255) << 8));
                    uint16_t pl = (uint16_t)((l0 & 255) | ((l1 & 255) << 8));
                    *(uint16_t*)(Q8h + (size_t)bz * sC + grow * N + gcol) = ph;
                    *(uint16_t*)(Q8l + (size_t)bz * sC + grow * N + gcol) = pl;
                } else {
                    *(float2*)(Cf + (size_t)bz * sC + grow * N + gcol) = make_float2(v0, v1);
                }
            }
        }
    }
}

// ======================= int8 fixed-point GEMM2 =======================
// logits = q·m^T / (SQ·SM) with q=qh*256+ql, m=mh*256+ml (s8 limbs), 4 exact s32 terms.
// CTA 128(M) x 128(N), 256 thr = 8 warps (2x4), warp tile 64x32.
// K-chunk 128 (one 128B s8 row), XOR-swizzled, 2 stages. Epilogue: scale + mask NEG -> fp32.

#define S8TILE (128 * ROWB)            // 16384: one 128-row s8 plane per chunk
#define S8STAGE (4 * S8TILE)           // 65536: qh, ql, mh, ml
#define S8SMEM (2 * S8STAGE)           // 131072

__device__ __forceinline__ void load_tile8(uint32_t st, const int8_t* g, int K, int k0, int tid) {
    #pragma unroll
    for (int p = 0; p < 4; p++) {
        int idx = p * 256 + tid;          // 0..1023 = 128 rows x 8 chunks
        int row = idx >> 3, c = idx & 7;
        cp16(st + (uint32_t)row * ROWB + (uint32_t)((c ^ (row & 7)) << 4),
             g + (size_t)row * K + k0 + c * 16);
    }
}

__global__ __launch_bounds__(256)
void gemm_s8(const int8_t* __restrict__ Ah, const int8_t* __restrict__ Al,
             const int8_t* __restrict__ Bh, const int8_t* __restrict__ Bl,
             const int* __restrict__ mask, float* __restrict__ Cf,
             int N, int K, size_t sA, size_t sB, size_t sC)
{
    extern __shared__ __align__(128) char dynsmem[];
    const int tid  = threadIdx.x;
    const int bz   = blockIdx.z;
    const int bm   = blockIdx.y * 128;
    const int bn   = blockIdx.x * 128;
    const int wid  = tid >> 5;
    const int lane = tid & 31;
    const int wm   = (wid >> 2) * 64;     // 0, 64
    const int wn   = (wid & 3) * 32;      // 0, 32, 64, 96

    const uint32_t sb = smem_u32(dynsmem);

    const int8_t* pAh = Ah + (size_t)bz * sA + (size_t)bm * K;
    const int8_t* pAl = Al + (size_t)bz * sA + (size_t)bm * K;
    const int8_t* pBh = Bh + (size_t)bz * sB + (size_t)bn * K;
    const int8_t* pBl = Bl + (size_t)bz * sB + (size_t)bn * K;

    int hh[4][4][4], md[4][4][4], ll[4][4][4];
    #pragma unroll
    for (int i = 0; i < 4; i++)
        #pragma unroll
        for (int j = 0; j < 4; j++)
            #pragma unroll
            for (int r = 0; r < 4; r++) { hh[i][j][r] = 0; md[i][j][r] = 0; ll[i][j][r] = 0; }

    const int nk = K >> 7;   // 128-wide k-chunks

    {
        load_tile8(sb,            pAh, K, 0, tid);
        load_tile8(sb +   S8TILE, pAl, K, 0, tid);
        load_tile8(sb + 2*S8TILE, pBh, K, 0, tid);
        load_tile8(sb + 3*S8TILE, pBl, K, 0, tid);
        asm volatile("cp.async.commit_group;" ::: "memory");
    }

    const uint32_t rowoff = (uint32_t)(lane & 15) * ROWB;
    const int      key    = lane & 7;
    const int      cbase  = lane >> 4;

    for (int c = 0; c < nk; ++c) {
        asm volatile("cp.async.wait_group 0;" ::: "memory");
        __syncthreads();

        if (c + 1 < nk) {
            uint32_t st = sb + (uint32_t)((c + 1) & 1) * S8STAGE;
            int k0 = (c + 1) << 7;
            load_tile8(st,            pAh, K, k0, tid);
            load_tile8(st +   S8TILE, pAl, K, k0, tid);
            load_tile8(st + 2*S8TILE, pBh, K, k0, tid);
            load_tile8(st + 3*S8TILE, pBl, K, k0, tid);
            asm volatile("cp.async.commit_group;" ::: "memory");
        }

        const uint32_t st = sb + (uint32_t)(c & 1) * S8STAGE;
        const uint32_t aH = st +            (uint32_t)wm * ROWB + rowoff;
        const uint32_t aL = aH + S8TILE;
        const uint32_t bH = st + 2*S8TILE + (uint32_t)wn * ROWB + rowoff;
        const uint32_t bL = bH + S8TILE;

        #pragma unroll
        for (int kk = 0; kk < 4; kk++) {      // 4 x k32 per 128B row
            const uint32_t sw = (uint32_t)(((kk*2 + cbase) ^ key) << 4);
            uint32_t a1[4][4], b1[2][4];
            #pragma unroll
            for (int g = 0; g < 2; g++) ldmx4(b1[g], bH + (uint32_t)g * (16 * ROWB) + sw);
            #pragma unroll
            for (int mt = 0; mt < 4; mt++) ldmx4(a1[mt], aH + (uint32_t)mt * (16 * ROWB) + sw);

            // term hh: qh x mh
            #pragma unroll
            for (int mt = 0; mt < 4; mt++)
                #pragma unroll
                for (int nt = 0; nt < 4; nt++) {
                    const int g = nt >> 1, s = nt & 1;
                    mma_s8(hh[mt][nt], a1[mt], b1[g][s], b1[g][s + 2]);
                }
            // term mid: ql x mh
            uint32_t a2[4][4];
            #pragma unroll
            for (int mt = 0; mt < 4; mt++) ldmx4(a2[mt], aL + (uint32_t)mt * (16 * ROWB) + sw);
            #pragma unroll
            for (int mt = 0; mt < 4; mt++)
                #pragma unroll
                for (int nt = 0; nt < 4; nt++) {
                    const int g = nt >> 1, s = nt & 1;
                    mma_s8(md[mt][nt], a2[mt], b1[g][s], b1[g][s + 2]);
                }
            // terms with ml
            uint32_t b2[2][4];
            #pragma unroll
            for (int g = 0; g < 2; g++) ldmx4(b2[g], bL + (uint32_t)g * (16 * ROWB) + sw);
            // mid: qh x ml
            #pragma unroll
            for (int mt = 0; mt < 4; mt++)
                #pragma unroll
                for (int nt = 0; nt < 4; nt++) {
                    const int g = nt >> 1, s = nt & 1;
                    mma_s8(md[mt][nt], a1[mt], b2[g][s], b2[g][s + 2]);
                }
            // ll: ql x ml
            #pragma unroll
            for (int mt = 0; mt < 4; mt++)
                #pragma unroll
                for (int nt = 0; nt < 4; nt++) {
                    const int g = nt >> 1, s = nt & 1;
                    mma_s8(ll[mt][nt], a2[mt], b2[g][s], b2[g][s + 2]);
                }
        }
    }

    // ---------------- epilogue: combine limb scales, mask, fp32 out ----------------
    const int r0 = lane >> 2;
    const int c0 = (lane & 3) * 2;

    #pragma unroll
    for (int mt = 0; mt < 4; mt++) {
        #pragma unroll
        for (int half_ = 0; half_ < 2; half_++) {
            const size_t grow = (size_t)(bm + wm + mt * 16 + r0 + half_ * 8);
            #pragma unroll
            for (int nt = 0; nt < 4; nt++) {
                const int gcol = bn + wn + nt * 8 + c0;
                float v0 = ((float)hh[mt][nt][half_*2+0] * 65536.0f
                          + (float)md[mt][nt][half_*2+0] * 256.0f
                          + (float)ll[mt][nt][half_*2+0]) * INVS;
                float v1 = ((float)hh[mt][nt][half_*2+1] * 65536.0f
                          + (float)md[mt][nt][half_*2+1] * 256.0f
                          + (float)ll[mt][nt][half_*2+1]) * INVS;
                int2 mm = *(const int2*)(mask + (size_t)bz * sC + grow * N + gcol);
                float2 vv;
                vv.x = v0 + (mm.x ? 0.0f : NEGV);
                vv.y = v1 + (mm.y ? 0.0f : NEGV);
                *(float2*)(Cf + (size_t)bz * sC + grow * N + gcol) = vv;
            }
        }
    }
}

// ------------------------- elementwise split fp32 -> (hi,lo) fp16 -------------------------
__global__ __launch_bounds__(256)
void split_kernel(const float* __restrict__ x, __half* __restrict__ hi,
                  __half* __restrict__ lo, size_t n)
{
    size_t i = ((size_t)blockIdx.x * 256 + threadIdx.x) * 4;
    if (i >= n) return;
    float4 v = *(const float4*)(x + i);
    float f[4] = {v.x, v.y, v.z, v.w};
    uint32_t ph[2], pl[2];
    #pragma unroll
    for (int j = 0; j < 2; j++) {
        __half h0, l0, h1, l1;
        split2h(f[2*j], h0, l0); split2h(f[2*j+1], h1, l1);
        ph[j] = ((uint32_t)__half_as_ushort(h1) << 16) | __half_as_ushort(h0);
        pl[j] = ((uint32_t)__half_as_ushort(l1) << 16) | __half_as_ushort(l0);
    }
    *(uint2*)(hi + i) = make_uint2(ph[0], ph[1]);
    *(uint2*)(lo + i) = make_uint2(pl[0], pl[1]);
}

// ---- fused: memories fp32 -> s8 limb planes (mh8,ml8) + single-fp16 transposed ----
__global__ __launch_bounds__(256)
void mem_prep_kernel(const float* __restrict__ src,
                     int8_t* __restrict__ mh8, int8_t* __restrict__ ml8,
                     __half* __restrict__ th,
                     int R, int C)
{
    __shared__ float t[32][33];
    const int z = blockIdx.z;
    src += (size_t)z * R * C;
    mh8 += (size_t)z * R * C;  ml8 += (size_t)z * R * C;
    th  += (size_t)z * R * C;
    const int c0 = blockIdx.x * 32, r0 = blockIdx.y * 32;
    const int tx = threadIdx.x, ty = threadIdx.y;

    #pragma unroll
    for (int i = 0; i < 4; i++) {
        const int r = r0 + ty + 8*i;
        float v = src[(size_t)r * C + c0 + tx];
        t[ty + 8*i][tx] = v;
        int h, l;
        split2q(v, SMF, h, l);
        mh8[(size_t)r * C + c0 + tx] = (int8_t)h;
        ml8[(size_t)r * C + c0 + tx] = (int8_t)l;
    }
    __syncthreads();
    #pragma unroll
    for (int i = 0; i < 4; i++) {
        const int c = c0 + ty + 8*i;
        float v = t[tx][ty + 8*i];
        th[(size_t)c * R + r0 + tx] = __float2half_rn(v);
    }
}

// ------------------------- row softmax over LM, writes single-fp16 weights -------------------------
__global__ __launch_bounds__(256)
void softmax_kernel(const float* __restrict__ x, __half* __restrict__ w)
{
    const float* row = x + (size_t)blockIdx.x * LM;
    __half* rw = w + (size_t)blockIdx.x * LM;
    const int t = threadIdx.x;
    __shared__ float smax[8], ssum[8];

    float v[8];
    float m = -3.0e38f;
    #pragma unroll
    for (int i = 0; i < 8; i++) { v[i] = row[t + i*256]; m = fmaxf(m, v[i]); }
    #pragma unroll
    for (int o = 16; o > 0; o >>= 1) m = fmaxf(m, __shfl_xor_sync(0xFFFFFFFFu, m, o));
    if ((t & 31) == 0) smax[t >> 5] = m;
    __syncthreads();
    m = smax[0];
    #pragma unroll
    for (int i = 1; i < 8; i++) m = fmaxf(m, smax[i]);

    float s = 0.0f;
    #pragma unroll
    for (int i = 0; i < 8; i++) { v[i] = expf(v[i] - m); s += v[i]; }
    #pragma unroll
    for (int o = 16; o > 0; o >>= 1) s += __shfl_xor_sync(0xFFFFFFFFu, s, o);
    if ((t & 31) == 0) ssum[t >> 5] = s;
    __syncthreads();
    s = 0.0f;
    #pragma unroll
    for (int i = 0; i < 8; i++) s += ssum[i];
    const float inv = 1.0f / s;

    #pragma unroll
    for (int i = 0; i < 8; i++)
        rw[t + i*256] = __float2half_rn(v[i] * inv);
}

// ------------------------- launch -------------------------
extern "C" void kernel_launch(void* const* d_in, const int* in_sizes, int n_in,
                              void* d_out, int out_size)
{
    (void)in_sizes; (void)n_in; (void)out_size;
    const float* query    = (const float*)d_in[0];
    const float* memories = (const float*)d_in[1];
    const int*   mask     = (const int*)d_in[2];
    const float* W        = (const float*)d_in[3];
    const float* bvec     = (const float*)d_in[4];
    float*       out      = (float*)d_out;

    __half *qryh, *qryl, *Wh, *Wl, *mTh, *w;
    int8_t *qh8, *ql8, *mh8, *ml8;
    float *logits;
    cudaGetSymbolAddress((void**)&qryh, g_qryh);  cudaGetSymbolAddress((void**)&qryl, g_qryl);
    cudaGetSymbolAddress((void**)&Wh,   g_Wh);    cudaGetSymbolAddress((void**)&Wl,   g_Wl);
    cudaGetSymbolAddress((void**)&qh8,  g_qh8);   cudaGetSymbolAddress((void**)&ql8,  g_ql8);
    cudaGetSymbolAddress((void**)&mh8,  g_mh8);   cudaGetSymbolAddress((void**)&ml8,  g_ml8);
    cudaGetSymbolAddress((void**)&mTh,  g_mTh);
    cudaGetSymbolAddress((void**)&w,    g_w);
    cudaGetSymbolAddress((void**)&logits, g_logits);

    const int SMEMF = NSTAGE * STAGEB;   // 196608
    cudaFuncSetAttribute(gemm_f16<1>, cudaFuncAttributeMaxDynamicSharedMemorySize, SMEMF);
    cudaFuncSetAttribute(gemm_f16<3>, cudaFuncAttributeMaxDynamicSharedMemorySize, SMEMF);
    cudaFuncSetAttribute(gemm_s8,     cudaFuncAttributeMaxDynamicSharedMemorySize, S8SMEM);

    const size_t nQ = (size_t)BB * LQ * DD;
    const size_t nW = (size_t)DD * DD;

    // 0) prep
    split_kernel<<<(unsigned)(nQ / 1024), 256>>>(query, qryh, qryl, nQ);
    split_kernel<<<(unsigned)(nW / 1024), 256>>>(W,     Wh,   Wl,   nW);
    mem_prep_kernel<<<dim3(DD/32, LM/32, BB), dim3(32, 8)>>>(memories, mh8, ml8, mTh, LM, DD);

    // 1) q = query @ W^T + b  (fp16 3-term) -> s8 limb planes (qh8, ql8)
    gemm_f16<1><<<dim3(DD/256, (BB*LQ)/128, 1), 256, SMEMF>>>(
        qryh, qryl, Wh, Wl, bvec, nullptr, qh8, ql8,
        DD, DD, (size_t)0, (size_t)0, (size_t)0);

    // 2) logits = q @ m^T / (SQ*SM) + mask  (int8 4-term exact) -> fp32
    gemm_s8<<<dim3(LM/128, LQ/128, BB), 256, S8SMEM>>>(
        qh8, ql8, mh8, ml8, mask, logits,
        LM, DD, (size_t)LQ*DD, (size_t)LM*DD, (size_t)LQ*LM);

    // 3) softmax -> fp16 weights
    softmax_kernel<<<BB*LQ, 256>>>(logits, w);

    // 4) out = w @ mTh^T  (fp16 1-term) -> fp32
    gemm_f16<3><<<dim3(DD/256, LQ/128, BB), 256, SMEMF>>>(
        w, nullptr, mTh, nullptr, nullptr, out, nullptr, nullptr,
        DD, LM, (size_t)LQ*LM, (size_t)DD*LM, (size_t)LQ*DD);
}